// round 13
// baseline (speedup 1.0000x reference)
#include <cuda_runtime.h>
#include <math.h>

#define Bb 4
#define Tt 12
#define NN 2000
#define KK 8
#define KMAX 16
#define CC 32
#define NBT (Bb*Tt)          // 48
#define TOT (Bb*Tt*NN)
#define TB  16               // bt per stage2 group
#define CH  8                // stage2 chunk
#define NTB (NBT/TB)         // 3
#define NG2 (NN*NTB)         // 6000 stage2 groups
#define HBT 24               // bt per stage1f warp (half of 48)

// ---- scratch (no allocations allowed) ----
__device__ float2 g_nwi[NN][KMAX];     // adj top-k (weight, idx-as-bits)
__device__ int    g_M[NN];
__device__ int    g_cnt[NN];
__device__ float  g_inv[NN];
__device__ float  g_h1[(size_t)TOT * CC];
__device__ float  g_XT[NN * NBT];      // X transposed: [n][bt]
__device__ float4 g_Te3[CC * CC];      // folded Theta1 (s=log1p(8)): [f*32+o]={q0..q3}
__device__ float4 g_TeA[CC * CC];
__device__ float4 g_TeB[CC * CC];
__device__ float4 g_TeC[CC * CC];
__device__ float4 g_Wt1v[8 * CC];      // Wt1: [q*32+o] = Wt1[o][4q..4q+3]

typedef unsigned long long ull;

__device__ __forceinline__ float maskf(float v) {
    if (isnan(v)) v = 6.0f;
    if (isinf(v)) v = 0.0f;
    return fminf(v, 6.0f);
}
__device__ __forceinline__ float ftanh(float x) {
    float e = __expf(2.0f * x);
    return 1.0f - __fdividef(2.0f, e + 1.0f);
}
__device__ __forceinline__ ull pk2(float a, float b) {
    ull r; asm("mov.b64 %0, {%1,%2};" : "=l"(r) : "f"(a), "f"(b)); return r;
}
__device__ __forceinline__ void upk2(ull v, float& a, float& b) {
    asm("mov.b64 {%0,%1}, %2;" : "=f"(a), "=f"(b) : "l"(v));
}
__device__ __forceinline__ ull fma2(ull a, ull b, ull c) {
    ull d; asm("fma.rn.f32x2 %0, %1, %2, %3;" : "=l"(d) : "l"(a), "l"(b), "l"(c)); return d;
}
__device__ __forceinline__ ull add2(ull a, ull b) {
    ull d; asm("add.rn.f32x2 %0, %1, %2;" : "=l"(d) : "l"(a), "l"(b)); return d;
}
// order-preserving float<->uint (total order incl. -inf)
__device__ __forceinline__ unsigned ford(float x) {
    unsigned u = __float_as_uint(x);
    return ((int)u >= 0) ? (u | 0x80000000u) : ~u;
}
__device__ __forceinline__ float funord(unsigned o) {
    unsigned u = (o & 0x80000000u) ? (o & 0x7fffffffu) : ~o;
    return __uint_as_float(u);
}

#define INS(xx) do { float x_ = (xx); \
    v7 = fmaxf(v7, fminf(v6, x_)); \
    v6 = fmaxf(v6, fminf(v5, x_)); \
    v5 = fmaxf(v5, fminf(v4, x_)); \
    v4 = fmaxf(v4, fminf(v3, x_)); \
    v3 = fmaxf(v3, fminf(v2, x_)); \
    v2 = fmaxf(v2, fminf(v1, x_)); \
    v1 = fmaxf(v1, fminf(v0, x_)); \
    v0 = fmaxf(v0, x_); } while(0)

#define MERGE8_THR() do { \
    _Pragma("unroll") \
    for (int k_ = 0; k_ < 8; k_++) { \
        unsigned mo_ = __reduce_max_sync(0xffffffffu, ford(v0)); \
        thr = funord(mo_); \
        unsigned msk_ = __ballot_sync(0xffffffffu, ford(v0) == mo_); \
        if (lane == (__ffs(msk_) - 1)) { \
            v0=v1; v1=v2; v2=v3; v3=v4; v4=v5; v5=v6; v6=v7; v7=-INFINITY; \
        } \
    } \
} while(0)

// ================= K1: topk(adj) [blocks 0-249] + prep [250-254] + XT [255-629]
__global__ void __launch_bounds__(256) setup0_kernel(const float* __restrict__ adj,
                                                     const float* __restrict__ Theta1,
                                                     const float* __restrict__ Wt1,
                                                     const float* __restrict__ X) {
    __shared__ float2 sCand[8][32][8];    // 16 KB
    int b = blockIdx.x;
    int tid = threadIdx.x;
    if (b >= 255) {
        int idx = (b - 255) * 256 + tid;
        g_XT[idx] = X[(idx % NBT) * NN + idx / NBT];
        return;
    }
    if (b >= 250) {
        int idx = (b - 250) * 256 + tid;
        if (idx < CC * CC) {
            int f = idx >> 5, o = idx & 31;
            const float s8  = log1pf(8.0f);
            const float is8 = 1.0f / s8;
            float4 va, vb, vc, ve;
            float *pa=(float*)&va, *pb=(float*)&vb, *pc=(float*)&vc, *pe=(float*)&ve;
            #pragma unroll
            for (int q = 0; q < 4; q++) {
                int src = (q * CC + f) * CC + o;
                float A = Theta1[src];
                float B = Theta1[4*CC*CC + src];
                float C = Theta1[8*CC*CC + src];
                pa[q] = A; pb[q] = B; pc[q] = C;
                pe[q] = A + s8 * B + is8 * C;
            }
            g_TeA[idx] = va; g_TeB[idx] = vb; g_TeC[idx] = vc; g_Te3[idx] = ve;
        } else if (idx < CC * CC + 8 * CC) {
            int i = idx - CC * CC;
            int q = i >> 5, o = i & 31;
            g_Wt1v[i] = ((const float4*)Wt1)[o * 8 + q];
        }
        return;
    }
    // ---- top-K of adj: warp per row ----
    int w = tid >> 5;
    int row = b * 8 + w;
    const float4* src4 = (const float4*)(adj + (size_t)row * NN);
    int lane = tid & 31;
    unsigned lt = (1u << lane) - 1u;

    const float CUT = 0.99f;
    int cnt = 0;
    #pragma unroll
    for (int t = 0; t < 16; t++) {
        int i4 = lane + t * 32;
        float4 f;
        if (i4 < 500) f = __ldg(&src4[i4]);
        else { f.x=f.y=f.z=f.w=-INFINITY; }
        int ib = 4 * i4;
        #pragma unroll
        for (int s = 0; s < 4; s++) {
            float x = (s==0)?f.x:(s==1)?f.y:(s==2)?f.z:f.w;
            if (x > CUT) {
                if (cnt < 8) sCand[w][lane][cnt] = make_float2(x, __int_as_float(ib + s));
                cnt++;
            }
        }
    }
    int total = __reduce_add_sync(0xffffffffu, (unsigned)cnt);
    int maxc  = __reduce_max_sync(0xffffffffu, (unsigned)cnt);
    bool fastp = (total >= KK) && (maxc <= 8);

    float v0=-INFINITY,v1=-INFINITY,v2=-INFINITY,v3=-INFINITY,
          v4=-INFINITY,v5=-INFINITY,v6=-INFINITY,v7=-INFINITY;
    if (fastp) {
        for (int k = 0; k < cnt; k++) INS(sCand[w][lane][k].x);
    } else {
        for (int t = 0; t < 16; t++) {
            int i4 = lane + t * 32;
            if (i4 < 500) {
                float4 f = __ldg(&src4[i4]);
                INS(f.x); INS(f.y); INS(f.z); INS(f.w);
            }
        }
    }

    float thr = -INFINITY;
    MERGE8_THR();

    bool done = false;
    if (fastp) {
        int cgt = 0, ceq = 0;
        float sgt = 0.f;
        for (int k = 0; k < maxc; k++) {
            bool act = k < cnt;
            float2 e = act ? sCand[w][lane][k] : make_float2(-INFINITY, 0.f);
            bool gt = act && (e.x >  thr);
            bool eq = act && (e.x == thr);
            unsigned mgt = __ballot_sync(0xffffffffu, gt);
            unsigned meq = __ballot_sync(0xffffffffu, eq);
            if (gt) {
                int p = cgt + __popc(mgt & lt);
                if (p < 8) g_nwi[row][p] = e;
                sgt += e.x;
            }
            cgt += __popc(mgt);
            if (eq) {
                int p = ceq + __popc(meq & lt);
                if (p < 8) g_nwi[row][8 + p] = e;
            }
            ceq += __popc(meq);
        }
        #pragma unroll
        for (int off = 16; off > 0; off >>= 1)
            sgt += __shfl_xor_sync(0xffffffffu, sgt, off);
        if (cgt + ceq == KK) {
            if (lane == 0) {
                for (int e2 = 0; e2 < ceq; e2++)
                    g_nwi[row][cgt + e2] = g_nwi[row][8 + e2];
                g_M[row]   = KK;
                g_cnt[row] = KK;
                g_inv[row] = 1.0f / (sgt + (float)ceq * thr);
            }
            done = true;
        }
    }

    if (!done) {
        int cgt = 0, ceq = 0;
        float sgt = 0.f;
        for (int t = 0; t < 16; t++) {
            int i4 = lane + t * 32;
            float4 f;
            if (i4 < 500) f = __ldg(&src4[i4]);
            else { f.x=f.y=f.z=f.w=-INFINITY; }
            bool any = (f.x >= thr) | (f.y >= thr) | (f.z >= thr) | (f.w >= thr);
            if (__ballot_sync(0xffffffffu, any) == 0u) continue;
            int ib = 4 * i4;
            #pragma unroll
            for (int s = 0; s < 4; s++) {
                float x = (s==0)?f.x:(s==1)?f.y:(s==2)?f.z:f.w;
                int   i = ib + s;
                bool gt = x >  thr;
                bool ge = x >= thr;
                unsigned mgt = __ballot_sync(0xffffffffu, gt);
                unsigned mge = __ballot_sync(0xffffffffu, ge);
                unsigned meq = mge & ~mgt;
                if (gt) {
                    int p = cgt + __popc(mgt & lt);
                    g_nwi[row][p] = make_float2(x, __int_as_float(i));
                    sgt += x;
                }
                cgt += __popc(mgt);
                if (meq) {
                    if (ge && !gt) {
                        int p = ceq + __popc(meq & lt);
                        if (p < 8) g_nwi[row][8 + p] = make_float2(x, __int_as_float(i));
                    }
                    ceq += __popc(meq);
                }
            }
        }
        #pragma unroll
        for (int off = 16; off > 0; off >>= 1)
            sgt += __shfl_xor_sync(0xffffffffu, sgt, off);

        if (lane == 0) {
            int cnt2 = cgt + ceq;
            int eq_stored = ceq < 8 ? ceq : 8;
            int M = cgt + eq_stored;
            for (int e2 = 0; e2 < eq_stored; e2++)
                g_nwi[row][cgt + e2] = g_nwi[row][8 + e2];
            g_M[row]   = M;
            g_cnt[row] = cnt2;
            g_inv[row] = 1.0f / (sgt + (float)ceq * thr);
        }
    }
}

// ================= K2: fused topk(adjm) + stage1, 2 warps per n ==============
// warp = (n, half): topk done redundantly per half (2nd read hits L2);
// each warp covers 24 of the 48 bt. Doubles warp-level parallelism.
__global__ void __launch_bounds__(256) stage1f_kernel(const float* __restrict__ adjm,
                              const float* __restrict__ Theta0,
                              const float* __restrict__ bias0,
                              const float* __restrict__ Wt0,
                              const float* __restrict__ bt0) {
    __shared__ float2 sCand[8][32][8];   // 16 KB
    __shared__ float2 sList[8][16];      // 1 KB
    __shared__ float4 sStat[8][HBT];     // 3 KB
    __shared__ float2 sR[8][4 * CC];     // 8 KB (4-pair staging)
    int tid = threadIdx.x;
    int lane = tid & 31;
    int w    = tid >> 5;
    int gw2 = blockIdx.x * 8 + w;        // 500*8 = 4000 = 2000 n x 2 halves
    int n = gw2 >> 1;
    int h = gw2 & 1;
    unsigned lt = (1u << lane) - 1u;

    // --------- topk of adjm row n ---------
    const float4* src4 = (const float4*)(adjm + (size_t)n * NN);
    const float CUT = 0.99f;
    int cnt = 0;
    #pragma unroll
    for (int t = 0; t < 16; t++) {
        int i4 = lane + t * 32;
        float4 f;
        if (i4 < 500) f = __ldg(&src4[i4]);
        else { f.x=f.y=f.z=f.w=-INFINITY; }
        int ib = 4 * i4;
        #pragma unroll
        for (int s = 0; s < 4; s++) {
            float x = (s==0)?f.x:(s==1)?f.y:(s==2)?f.z:f.w;
            if (x > CUT) {
                if (cnt < 8) sCand[w][lane][cnt] = make_float2(x, __int_as_float(ib + s));
                cnt++;
            }
        }
    }
    int total = __reduce_add_sync(0xffffffffu, (unsigned)cnt);
    int maxc  = __reduce_max_sync(0xffffffffu, (unsigned)cnt);
    bool fastp = (total >= KK) && (maxc <= 8);

    float v0=-INFINITY,v1=-INFINITY,v2=-INFINITY,v3=-INFINITY,
          v4=-INFINITY,v5=-INFINITY,v6=-INFINITY,v7=-INFINITY;
    if (fastp) {
        for (int k = 0; k < cnt; k++) INS(sCand[w][lane][k].x);
    } else {
        for (int t = 0; t < 16; t++) {
            int i4 = lane + t * 32;
            if (i4 < 500) {
                float4 f = __ldg(&src4[i4]);
                INS(f.x); INS(f.y); INS(f.z); INS(f.w);
            }
        }
    }

    float thr = -INFINITY;
    MERGE8_THR();

    int Mv = 0;
    int cgtF = 0;
    float inv = 0.f;
    bool done = false;
    if (fastp) {
        int cgt = 0, ceq = 0;
        float sgt = 0.f;
        for (int k = 0; k < maxc; k++) {
            bool act = k < cnt;
            float2 e = act ? sCand[w][lane][k] : make_float2(-INFINITY, 0.f);
            bool gt = act && (e.x >  thr);
            bool eq = act && (e.x == thr);
            unsigned mgt = __ballot_sync(0xffffffffu, gt);
            unsigned meq = __ballot_sync(0xffffffffu, eq);
            if (gt) {
                int p = cgt + __popc(mgt & lt);
                if (p < 8) sList[w][p] = e;
                sgt += e.x;
            }
            cgt += __popc(mgt);
            if (eq) {
                int p = ceq + __popc(meq & lt);
                if (p < 8) sList[w][8 + p] = e;
            }
            ceq += __popc(meq);
        }
        #pragma unroll
        for (int off = 16; off > 0; off >>= 1)
            sgt += __shfl_xor_sync(0xffffffffu, sgt, off);
        if (cgt + ceq == KK) {
            Mv = KK; cgtF = cgt;
            inv = 1.0f / (sgt + (float)ceq * thr);
            done = true;
        }
    }
    __syncwarp();

    float wreg = 0.f; int ireg = 0;
    if (done) {
        if (lane < KK) {
            float2 e = (lane < cgtF) ? sList[w][lane] : sList[w][8 + lane - cgtF];
            wreg = e.x; ireg = __float_as_int(e.y);
        }
    } else {
        int cgt = 0, ceq = 0;
        float sgt = 0.f;
        for (int t = 0; t < 16; t++) {
            int i4 = lane + t * 32;
            float4 f;
            if (i4 < 500) f = __ldg(&src4[i4]);
            else { f.x=f.y=f.z=f.w=-INFINITY; }
            bool any = (f.x >= thr) | (f.y >= thr) | (f.z >= thr) | (f.w >= thr);
            if (__ballot_sync(0xffffffffu, any) == 0u) continue;
            int ib = 4 * i4;
            #pragma unroll
            for (int s = 0; s < 4; s++) {
                float x = (s==0)?f.x:(s==1)?f.y:(s==2)?f.z:f.w;
                int   i = ib + s;
                bool gt = x >  thr;
                bool ge = x >= thr;
                unsigned mgt = __ballot_sync(0xffffffffu, gt);
                unsigned mge = __ballot_sync(0xffffffffu, ge);
                unsigned meq = mge & ~mgt;
                if (gt) {
                    int p = cgt + __popc(mgt & lt);
                    if (p < 8) sList[w][p] = make_float2(x, __int_as_float(i));
                    sgt += x;
                }
                cgt += __popc(mgt);
                if (meq) {
                    if (ge && !gt) {
                        int p = ceq + __popc(meq & lt);
                        if (p < 8) sList[w][8 + p] = make_float2(x, __int_as_float(i));
                    }
                    ceq += __popc(meq);
                }
            }
        }
        #pragma unroll
        for (int off = 16; off > 0; off >>= 1)
            sgt += __shfl_xor_sync(0xffffffffu, sgt, off);
        int eq_stored = ceq < 8 ? ceq : 8;
        Mv  = cgt + eq_stored;
        inv = 1.0f / (sgt + (float)ceq * thr);
        __syncwarp();
        if (lane < Mv) {
            float2 e = (lane < cgt) ? sList[w][lane] : sList[w][8 + lane - cgt];
            wreg = e.x; ireg = __float_as_int(e.y);
        }
    }
    __syncwarp();

    // --------- stage1 body for 24 bt (lane = local bt) ---------
    float b0  = __ldg(&bias0[lane]), btc = __ldg(&bt0[lane]);
    ull t0m = pk2(__ldg(&Theta0[lane]),        __ldg(&Theta0[lane]));
    ull t0x = pk2(__ldg(&Theta0[CC+lane]),     __ldg(&Theta0[CC+lane]));
    ull t0n = pk2(__ldg(&Theta0[2*CC+lane]),   __ldg(&Theta0[2*CC+lane]));
    ull t0s = pk2(__ldg(&Theta0[3*CC+lane]),   __ldg(&Theta0[3*CC+lane]));
    float4 wv[8];
    #pragma unroll
    for (int q = 0; q < 8; q++) wv[q] = __ldg(&((const float4*)Wt0)[lane * 8 + q]);

    bool act = lane < HBT;
    int btl = h * HBT + (act ? lane : 0);

    float sw0 = 0.f, sq0 = 0.f, mx0 = -INFINITY, mn0 = INFINITY;
    if (Mv == KK) {
        #pragma unroll
        for (int j = 0; j < KK; j++) {
            float wtj = __shfl_sync(0xffffffffu, wreg, j);
            int   mij = __shfl_sync(0xffffffffu, ireg, j);
            float x0 = __ldg(g_XT + mij * NBT + btl);
            float t0 = wtj * x0;
            sw0 += t0; sq0 += t0 * x0;
            if (wtj > 0.f) { mx0 = fmaxf(mx0, x0); mn0 = fminf(mn0, x0); }
        }
    } else {
        for (int j = 0; j < Mv; j++) {
            float wtj = __shfl_sync(0xffffffffu, wreg, j);
            int   mij = __shfl_sync(0xffffffffu, ireg, j);
            float x0 = __ldg(g_XT + mij * NBT + btl);
            float t0 = wtj * x0;
            sw0 += t0; sq0 += t0 * x0;
            if (j < KK && wtj > 0.f) { mx0 = fmaxf(mx0, x0); mn0 = fminf(mn0, x0); }
        }
    }
    if (act) {
        float mean = sw0 * inv;
        float sd = sqrtf(fmaxf(sq0 * inv - mean * mean, 0.f) + 1e-5f);
        sStat[w][lane] = make_float4(maskf(mean), maskf(mx0), maskf(mn0), maskf(sd));
    }
    __syncwarp();

    ull b02 = pk2(b0, b0), btc2 = pk2(btc, btc);
    #pragma unroll
    for (int s = 0; s < 3; s++) {               // 3 sub-batches of 4 pairs
        int base = s * 8;                       // local bt base
        float2* rp = &sR[w][0];
        ull racc[4];
        #pragma unroll
        for (int p = 0; p < 4; p++) {
            float4 A = sStat[w][base + 2 * p];
            float4 B = sStat[w][base + 2 * p + 1];
            ull o2 = b02;
            o2 = fma2(pk2(A.x, B.x), t0m, o2);
            o2 = fma2(pk2(A.y, B.y), t0x, o2);
            o2 = fma2(pk2(A.z, B.z), t0n, o2);
            o2 = fma2(pk2(A.w, B.w), t0s, o2);
            float f0, f1; upk2(o2, f0, f1);
            rp[p * CC + lane] = make_float2(f0, f1);
            racc[p] = o2;
        }
        __syncwarp();
        ull acc2[4];
        #pragma unroll
        for (int p = 0; p < 4; p++) acc2[p] = add2(btc2, racc[p]);
        #pragma unroll
        for (int q = 0; q < 8; q++) {
            ull wx = pk2(wv[q].x, wv[q].x), wy = pk2(wv[q].y, wv[q].y);
            ull wz = pk2(wv[q].z, wv[q].z), ww2 = pk2(wv[q].w, wv[q].w);
            #pragma unroll
            for (int p = 0; p < 4; p++) {
                const ulonglong2* rr = (const ulonglong2*)&rp[p * CC + 4 * q];
                ulonglong2 ra = rr[0];
                ulonglong2 rb = rr[1];
                acc2[p] = fma2(ra.x, wx, acc2[p]);
                acc2[p] = fma2(ra.y, wy, acc2[p]);
                acc2[p] = fma2(rb.x, wz, acc2[p]);
                acc2[p] = fma2(rb.y, ww2, acc2[p]);
            }
        }
        #pragma unroll
        for (int p = 0; p < 4; p++) {
            float a0, a1; upk2(acc2[p], a0, a1);
            int bt = h * HBT + base + 2 * p;
            g_h1[((size_t)bt * NN + n) * CC + lane]       = ftanh(a0);
            g_h1[((size_t)(bt + 1) * NN + n) * CC + lane] = ftanh(a1);
        }
        __syncwarp();
    }
}
#undef INS

// ================= K3: stage2, neighbor list in smem, occ 8 blocks ==========
__global__ void __launch_bounds__(128, 8) stage2_kernel(const float* __restrict__ bias1,
                              const float* __restrict__ bt1,
                              const float* __restrict__ Wout,
                              const float* __restrict__ bout,
                              float* __restrict__ out) {
    __shared__ float4 sP[4][4][2][CC];   // 16 KB
    __shared__ float2 sLst[4][16];       // 512 B per-warp neighbor lists
    int tid = threadIdx.x;
    int lane = tid & 31;
    int w    = tid >> 5;

    float b1 = __ldg(&bias1[lane]), btc = __ldg(&bt1[lane]);
    float wo = __ldg(&Wout[lane]),  bo  = __ldg(&bout[0]);

    int grp = blockIdx.x * 4 + w;
    if (grp >= NG2) return;
    int n  = grp / NTB;
    int tb = grp - n * NTB;
    int bt0v = tb * TB;

    int M   = g_M[n];
    int cnt = g_cnt[n];
    float inv = g_inv[n];
    bool fast = (cnt == KK);

    if (lane < 16)
        sLst[w][lane] = (lane < M) ? g_nwi[n][lane] : make_float2(0.f, 0.f);
    __syncwarp();

    ull btc2 = pk2(btc, btc);

    #pragma unroll
    for (int ch = 0; ch < 2; ch++) {
        int btc0 = bt0v + ch * CH;
        float sw[CH], sq[CH], mxv[CH], mnv[CH];
        #pragma unroll
        for (int u = 0; u < CH; u++) {
            sw[u] = 0.f; sq[u] = 0.f; mxv[u] = -INFINITY; mnv[u] = INFINITY;
        }
        size_t cbase = (size_t)btc0 * NN * CC + lane;
        if (M == KK) {
            #pragma unroll
            for (int j = 0; j < KK; j++) {
                float2 wi = sLst[w][j];                  // uniform LDS
                const float* hp = g_h1 + cbase + (size_t)__float_as_int(wi.y) * CC;
                float wtj = wi.x;
                bool pos = wtj > 0.f;
                #pragma unroll
                for (int u = 0; u < CH; u++) {
                    float hv = __ldg(hp + (size_t)u * (NN * CC));
                    float t = wtj * hv;
                    sw[u] += t; sq[u] += t * hv;
                    if (pos) { mxv[u] = fmaxf(mxv[u], hv); mnv[u] = fminf(mnv[u], hv); }
                }
            }
        } else {
            for (int j = 0; j < M; j++) {
                float2 wi = sLst[w][j];
                const float* hp = g_h1 + cbase + (size_t)__float_as_int(wi.y) * CC;
                float wtj = wi.x;
                bool pos = (j < KK) && (wtj > 0.f);
                #pragma unroll
                for (int u = 0; u < CH; u++) {
                    float hv = __ldg(hp + (size_t)u * (NN * CC));
                    float t = wtj * hv;
                    sw[u] += t; sq[u] += t * hv;
                    if (pos) { mxv[u] = fmaxf(mxv[u], hv); mnv[u] = fminf(mnv[u], hv); }
                }
            }
        }
        #pragma unroll
        for (int u = 0; u < CH; u++) {
            float mean = sw[u] * inv;
            float sd = sqrtf(fmaxf(sq[u] * inv - mean * mean, 0.f) + 1e-5f);
            sw[u] = mean; sq[u] = sd;
        }
        #pragma unroll
        for (int p = 0; p < CH / 2; p++) {
            int u0 = 2 * p, u1 = 2 * p + 1;
            sP[w][p][0][lane] = make_float4(sw[u0], sw[u1], mxv[u0], mxv[u1]);
            sP[w][p][1][lane] = make_float4(mnv[u0], mnv[u1], sq[u0], sq[u1]);
        }
        __syncwarp();

        ull acc[4];
        #pragma unroll
        for (int p = 0; p < 4; p++) acc[p] = pk2(b1, b1);

        if (fast) {
            #pragma unroll 4
            for (int f = 0; f < CC; f++) {
                float4 wvv = __ldg(&g_Te3[f * CC + lane]);
                ull wx = pk2(wvv.x, wvv.x), wy = pk2(wvv.y, wvv.y);
                ull wz = pk2(wvv.z, wvv.z), ww2 = pk2(wvv.w, wvv.w);
                #pragma unroll
                for (int p = 0; p < 4; p++) {
                    ulonglong2 a = *(const ulonglong2*)&sP[w][p][0][f];
                    ulonglong2 bb = *(const ulonglong2*)&sP[w][p][1][f];
                    acc[p] = fma2(a.x, wx, acc[p]);
                    acc[p] = fma2(a.y, wy, acc[p]);
                    acc[p] = fma2(bb.x, wz, acc[p]);
                    acc[p] = fma2(bb.y, ww2, acc[p]);
                }
            }
        } else {
            float s  = log1pf((float)cnt);
            float is = 1.0f / s;
            for (int f = 0; f < CC; f++) {
                float4 a4 = __ldg(&g_TeA[f * CC + lane]);
                float4 b4 = __ldg(&g_TeB[f * CC + lane]);
                float4 c4 = __ldg(&g_TeC[f * CC + lane]);
                float4 wvv;
                wvv.x = a4.x + s * b4.x + is * c4.x;
                wvv.y = a4.y + s * b4.y + is * c4.y;
                wvv.z = a4.z + s * b4.z + is * c4.z;
                wvv.w = a4.w + s * b4.w + is * c4.w;
                ull wx = pk2(wvv.x, wvv.x), wy = pk2(wvv.y, wvv.y);
                ull wz = pk2(wvv.z, wvv.z), ww2 = pk2(wvv.w, wvv.w);
                #pragma unroll
                for (int p = 0; p < 4; p++) {
                    ulonglong2 a = *(const ulonglong2*)&sP[w][p][0][f];
                    ulonglong2 bb = *(const ulonglong2*)&sP[w][p][1][f];
                    acc[p] = fma2(a.x, wx, acc[p]);
                    acc[p] = fma2(a.y, wy, acc[p]);
                    acc[p] = fma2(bb.x, wz, acc[p]);
                    acc[p] = fma2(bb.y, ww2, acc[p]);
                }
            }
        }
        __syncwarp();

        float2* rp = (float2*)&sP[w][0][0][0];
        ull racc[4];
        #pragma unroll
        for (int p = 0; p < 4; p++) {
            float a0, a1; upk2(acc[p], a0, a1);
            float r0 = fmaxf(a0, 0.f), r1 = fmaxf(a1, 0.f);
            rp[p * 32 + lane] = make_float2(r0, r1);
            racc[p] = pk2(r0, r1);
        }
        __syncwarp();

        ull acc2[4];
        #pragma unroll
        for (int p = 0; p < 4; p++) acc2[p] = add2(btc2, racc[p]);
        #pragma unroll
        for (int q = 0; q < 8; q++) {
            float4 wq = __ldg(&g_Wt1v[q * CC + lane]);
            ull wx = pk2(wq.x, wq.x), wy = pk2(wq.y, wq.y);
            ull wz = pk2(wq.z, wq.z), ww2 = pk2(wq.w, wq.w);
            #pragma unroll
            for (int p = 0; p < 4; p++) {
                const ulonglong2* rr = (const ulonglong2*)&rp[p * 32 + 4 * q];
                ulonglong2 ra = rr[0];
                ulonglong2 rb = rr[1];
                acc2[p] = fma2(ra.x, wx, acc2[p]);
                acc2[p] = fma2(ra.y, wy, acc2[p]);
                acc2[p] = fma2(rb.x, wz, acc2[p]);
                acc2[p] = fma2(rb.y, ww2, acc2[p]);
            }
        }
        __syncwarp();

        #pragma unroll
        for (int p = 0; p < 4; p++) {
            float t0, t1; upk2(acc2[p], t0, t1);
            float u0 = fmaxf(ftanh(t0), 0.f);
            float u1 = fmaxf(ftanh(t1), 0.f);
            ull pu = pk2(wo * u0, wo * u1);
            #pragma unroll
            for (int off = 16; off > 0; off >>= 1)
                pu = add2(pu, __shfl_xor_sync(0xffffffffu, pu, off));
            if (lane == 0) {
                float s0, s1; upk2(pu, s0, s1);
                out[(size_t)(btc0 + 2 * p)     * NN + n] = s0 + bo;
                out[(size_t)(btc0 + 2 * p + 1) * NN + n] = s1 + bo;
            }
        }
        __syncwarp();
    }
}

extern "C" void kernel_launch(void* const* d_in, const int* in_sizes, int n_in,
                              void* d_out, int out_size) {
    const float* X      = (const float*)d_in[0];
    const float* adj    = (const float*)d_in[1];
    const float* adjm   = (const float*)d_in[2];
    const float* Theta0 = (const float*)d_in[3];
    const float* bias0  = (const float*)d_in[4];
    const float* Wt0    = (const float*)d_in[5];
    const float* bt0    = (const float*)d_in[6];
    const float* Theta1 = (const float*)d_in[7];
    const float* bias1  = (const float*)d_in[8];
    const float* Wt1    = (const float*)d_in[9];
    const float* bt1    = (const float*)d_in[10];
    const float* Wout   = (const float*)d_in[11];
    const float* bout   = (const float*)d_in[12];
    float* out = (float*)d_out;

    setup0_kernel<<<630, 256>>>(adj, Theta1, Wt1, X);
    stage1f_kernel<<<500, 256>>>(adjm, Theta0, bias0, Wt0, bt0);
    stage2_kernel<<<(NG2 + 3) / 4, 128>>>(bias1, bt1, Wout, bout, out);
}

// round 14
// speedup vs baseline: 1.1459x; 1.1459x over previous
#include <cuda_runtime.h>
#include <math.h>

#define Bb 4
#define Tt 12
#define NN 2000
#define KK 8
#define KMAX 16
#define CC 32
#define NBT (Bb*Tt)          // 48
#define TOT (Bb*Tt*NN)
#define TB  16               // bt per stage2 group
#define CH  8                // stage2 chunk
#define NTB (NBT/TB)         // 3
#define NG2 (NN*NTB)         // 6000 stage2 groups

// ---- scratch (no allocations allowed) ----
__device__ float2 g_nwi[NN][KMAX];     // adj top-k (weight, idx-as-bits)
__device__ int    g_M[NN];
__device__ int    g_cnt[NN];
__device__ float  g_inv[NN];
__device__ float  g_h1[(size_t)TOT * CC];
__device__ float  g_XT[NN * NBT];      // X transposed: [n][bt]
__device__ float4 g_Te3[CC * CC];      // folded Theta1 (s=log1p(8)): [f*32+o]={q0..q3}
__device__ float4 g_TeA[CC * CC];
__device__ float4 g_TeB[CC * CC];
__device__ float4 g_TeC[CC * CC];
__device__ float4 g_Wt1v[8 * CC];      // Wt1: [q*32+o] = Wt1[o][4q..4q+3]

typedef unsigned long long ull;

__device__ __forceinline__ float maskf(float v) {
    if (isnan(v)) v = 6.0f;
    if (isinf(v)) v = 0.0f;
    return fminf(v, 6.0f);
}
__device__ __forceinline__ float ftanh(float x) {
    float e = __expf(2.0f * x);
    return 1.0f - __fdividef(2.0f, e + 1.0f);
}
__device__ __forceinline__ ull pk2(float a, float b) {
    ull r; asm("mov.b64 %0, {%1,%2};" : "=l"(r) : "f"(a), "f"(b)); return r;
}
__device__ __forceinline__ void upk2(ull v, float& a, float& b) {
    asm("mov.b64 {%0,%1}, %2;" : "=f"(a), "=f"(b) : "l"(v));
}
__device__ __forceinline__ ull fma2(ull a, ull b, ull c) {
    ull d; asm("fma.rn.f32x2 %0, %1, %2, %3;" : "=l"(d) : "l"(a), "l"(b), "l"(c)); return d;
}
__device__ __forceinline__ ull add2(ull a, ull b) {
    ull d; asm("add.rn.f32x2 %0, %1, %2;" : "=l"(d) : "l"(a), "l"(b)); return d;
}
// order-preserving float<->uint (total order incl. -inf)
__device__ __forceinline__ unsigned ford(float x) {
    unsigned u = __float_as_uint(x);
    return ((int)u >= 0) ? (u | 0x80000000u) : ~u;
}
__device__ __forceinline__ float funord(unsigned o) {
    unsigned u = (o & 0x80000000u) ? (o & 0x7fffffffu) : ~o;
    return __uint_as_float(u);
}

#define INS(xx) do { float x_ = (xx); \
    v7 = fmaxf(v7, fminf(v6, x_)); \
    v6 = fmaxf(v6, fminf(v5, x_)); \
    v5 = fmaxf(v5, fminf(v4, x_)); \
    v4 = fmaxf(v4, fminf(v3, x_)); \
    v3 = fmaxf(v3, fminf(v2, x_)); \
    v2 = fmaxf(v2, fminf(v1, x_)); \
    v1 = fmaxf(v1, fminf(v0, x_)); \
    v0 = fmaxf(v0, x_); } while(0)

#define MERGE8_THR() do { \
    _Pragma("unroll") \
    for (int k_ = 0; k_ < 8; k_++) { \
        unsigned mo_ = __reduce_max_sync(0xffffffffu, ford(v0)); \
        thr = funord(mo_); \
        unsigned msk_ = __ballot_sync(0xffffffffu, ford(v0) == mo_); \
        if (lane == (__ffs(msk_) - 1)) { \
            v0=v1; v1=v2; v2=v3; v3=v4; v4=v5; v5=v6; v6=v7; v7=-INFINITY; \
        } \
    } \
} while(0)

// ================= K1: topk(adj) [blocks 0-249] + prep [250-254] + XT [255-629]
__global__ void __launch_bounds__(256) setup0_kernel(const float* __restrict__ adj,
                                                     const float* __restrict__ Theta1,
                                                     const float* __restrict__ Wt1,
                                                     const float* __restrict__ X) {
    __shared__ float2 sCand[8][32][8];    // 16 KB
    int b = blockIdx.x;
    int tid = threadIdx.x;
    if (b >= 255) {
        int idx = (b - 255) * 256 + tid;
        g_XT[idx] = X[(idx % NBT) * NN + idx / NBT];
        return;
    }
    if (b >= 250) {
        int idx = (b - 250) * 256 + tid;
        if (idx < CC * CC) {
            int f = idx >> 5, o = idx & 31;
            const float s8  = log1pf(8.0f);
            const float is8 = 1.0f / s8;
            float4 va, vb, vc, ve;
            float *pa=(float*)&va, *pb=(float*)&vb, *pc=(float*)&vc, *pe=(float*)&ve;
            #pragma unroll
            for (int q = 0; q < 4; q++) {
                int src = (q * CC + f) * CC + o;
                float A = Theta1[src];
                float B = Theta1[4*CC*CC + src];
                float C = Theta1[8*CC*CC + src];
                pa[q] = A; pb[q] = B; pc[q] = C;
                pe[q] = A + s8 * B + is8 * C;
            }
            g_TeA[idx] = va; g_TeB[idx] = vb; g_TeC[idx] = vc; g_Te3[idx] = ve;
        } else if (idx < CC * CC + 8 * CC) {
            int i = idx - CC * CC;
            int q = i >> 5, o = i & 31;
            g_Wt1v[i] = ((const float4*)Wt1)[o * 8 + q];
        }
        return;
    }
    // ---- top-K of adj: warp per row ----
    int w = tid >> 5;
    int row = b * 8 + w;
    const float4* src4 = (const float4*)(adj + (size_t)row * NN);
    int lane = tid & 31;
    unsigned lt = (1u << lane) - 1u;

    const float CUT = 0.99f;
    int cnt = 0;
    #pragma unroll
    for (int t = 0; t < 16; t++) {
        int i4 = lane + t * 32;
        float4 f;
        if (i4 < 500) f = __ldg(&src4[i4]);
        else { f.x=f.y=f.z=f.w=-INFINITY; }
        int ib = 4 * i4;
        #pragma unroll
        for (int s = 0; s < 4; s++) {
            float x = (s==0)?f.x:(s==1)?f.y:(s==2)?f.z:f.w;
            if (x > CUT) {
                if (cnt < 8) sCand[w][lane][cnt] = make_float2(x, __int_as_float(ib + s));
                cnt++;
            }
        }
    }
    int total = __reduce_add_sync(0xffffffffu, (unsigned)cnt);
    int maxc  = __reduce_max_sync(0xffffffffu, (unsigned)cnt);
    bool fastp = (total >= KK) && (maxc <= 8);

    float v0=-INFINITY,v1=-INFINITY,v2=-INFINITY,v3=-INFINITY,
          v4=-INFINITY,v5=-INFINITY,v6=-INFINITY,v7=-INFINITY;
    if (fastp) {
        for (int k = 0; k < cnt; k++) INS(sCand[w][lane][k].x);
    } else {
        for (int t = 0; t < 16; t++) {
            int i4 = lane + t * 32;
            if (i4 < 500) {
                float4 f = __ldg(&src4[i4]);
                INS(f.x); INS(f.y); INS(f.z); INS(f.w);
            }
        }
    }

    float thr = -INFINITY;
    MERGE8_THR();

    bool done = false;
    if (fastp) {
        int cgt = 0, ceq = 0;
        float sgt = 0.f;
        for (int k = 0; k < maxc; k++) {
            bool act = k < cnt;
            float2 e = act ? sCand[w][lane][k] : make_float2(-INFINITY, 0.f);
            bool gt = act && (e.x >  thr);
            bool eq = act && (e.x == thr);
            unsigned mgt = __ballot_sync(0xffffffffu, gt);
            unsigned meq = __ballot_sync(0xffffffffu, eq);
            if (gt) {
                int p = cgt + __popc(mgt & lt);
                if (p < 8) g_nwi[row][p] = e;
                sgt += e.x;
            }
            cgt += __popc(mgt);
            if (eq) {
                int p = ceq + __popc(meq & lt);
                if (p < 8) g_nwi[row][8 + p] = e;
            }
            ceq += __popc(meq);
        }
        #pragma unroll
        for (int off = 16; off > 0; off >>= 1)
            sgt += __shfl_xor_sync(0xffffffffu, sgt, off);
        if (cgt + ceq == KK) {
            if (lane == 0) {
                for (int e2 = 0; e2 < ceq; e2++)
                    g_nwi[row][cgt + e2] = g_nwi[row][8 + e2];
                g_M[row]   = KK;
                g_cnt[row] = KK;
                g_inv[row] = 1.0f / (sgt + (float)ceq * thr);
            }
            done = true;
        }
    }

    if (!done) {
        int cgt = 0, ceq = 0;
        float sgt = 0.f;
        for (int t = 0; t < 16; t++) {
            int i4 = lane + t * 32;
            float4 f;
            if (i4 < 500) f = __ldg(&src4[i4]);
            else { f.x=f.y=f.z=f.w=-INFINITY; }
            bool any = (f.x >= thr) | (f.y >= thr) | (f.z >= thr) | (f.w >= thr);
            if (__ballot_sync(0xffffffffu, any) == 0u) continue;
            int ib = 4 * i4;
            #pragma unroll
            for (int s = 0; s < 4; s++) {
                float x = (s==0)?f.x:(s==1)?f.y:(s==2)?f.z:f.w;
                int   i = ib + s;
                bool gt = x >  thr;
                bool ge = x >= thr;
                unsigned mgt = __ballot_sync(0xffffffffu, gt);
                unsigned mge = __ballot_sync(0xffffffffu, ge);
                unsigned meq = mge & ~mgt;
                if (gt) {
                    int p = cgt + __popc(mgt & lt);
                    g_nwi[row][p] = make_float2(x, __int_as_float(i));
                    sgt += x;
                }
                cgt += __popc(mgt);
                if (meq) {
                    if (ge && !gt) {
                        int p = ceq + __popc(meq & lt);
                        if (p < 8) g_nwi[row][8 + p] = make_float2(x, __int_as_float(i));
                    }
                    ceq += __popc(meq);
                }
            }
        }
        #pragma unroll
        for (int off = 16; off > 0; off >>= 1)
            sgt += __shfl_xor_sync(0xffffffffu, sgt, off);

        if (lane == 0) {
            int cnt2 = cgt + ceq;
            int eq_stored = ceq < 8 ? ceq : 8;
            int M = cgt + eq_stored;
            for (int e2 = 0; e2 < eq_stored; e2++)
                g_nwi[row][cgt + e2] = g_nwi[row][8 + e2];
            g_M[row]   = M;
            g_cnt[row] = cnt2;
            g_inv[row] = 1.0f / (sgt + (float)ceq * thr);
        }
    }
}

// ================= K2: fused topk(adjm) + stage1, warp per n (round-12) =====
__global__ void __launch_bounds__(256) stage1f_kernel(const float* __restrict__ adjm,
                              const float* __restrict__ Theta0,
                              const float* __restrict__ bias0,
                              const float* __restrict__ Wt0,
                              const float* __restrict__ bt0) {
    __shared__ float2 sCand[8][32][8];   // 16 KB
    __shared__ float2 sList[8][16];      // 1 KB  (slots [0..8)=gt, [8..16)=eq)
    __shared__ float4 sStat[8][NBT];     // 6 KB
    __shared__ float2 sR[8][8 * CC];     // 16 KB
    int tid = threadIdx.x;
    int lane = tid & 31;
    int w    = tid >> 5;
    int n = blockIdx.x * 8 + w;
    unsigned lt = (1u << lane) - 1u;

    const float4* src4 = (const float4*)(adjm + (size_t)n * NN);
    const float CUT = 0.99f;
    int cnt = 0;
    #pragma unroll
    for (int t = 0; t < 16; t++) {
        int i4 = lane + t * 32;
        float4 f;
        if (i4 < 500) f = __ldg(&src4[i4]);
        else { f.x=f.y=f.z=f.w=-INFINITY; }
        int ib = 4 * i4;
        #pragma unroll
        for (int s = 0; s < 4; s++) {
            float x = (s==0)?f.x:(s==1)?f.y:(s==2)?f.z:f.w;
            if (x > CUT) {
                if (cnt < 8) sCand[w][lane][cnt] = make_float2(x, __int_as_float(ib + s));
                cnt++;
            }
        }
    }
    int total = __reduce_add_sync(0xffffffffu, (unsigned)cnt);
    int maxc  = __reduce_max_sync(0xffffffffu, (unsigned)cnt);
    bool fastp = (total >= KK) && (maxc <= 8);

    float v0=-INFINITY,v1=-INFINITY,v2=-INFINITY,v3=-INFINITY,
          v4=-INFINITY,v5=-INFINITY,v6=-INFINITY,v7=-INFINITY;
    if (fastp) {
        for (int k = 0; k < cnt; k++) INS(sCand[w][lane][k].x);
    } else {
        for (int t = 0; t < 16; t++) {
            int i4 = lane + t * 32;
            if (i4 < 500) {
                float4 f = __ldg(&src4[i4]);
                INS(f.x); INS(f.y); INS(f.z); INS(f.w);
            }
        }
    }

    float thr = -INFINITY;
    MERGE8_THR();

    int Mv = 0;
    int cgtF = 0;
    float inv = 0.f;
    bool done = false;
    if (fastp) {
        int cgt = 0, ceq = 0;
        float sgt = 0.f;
        for (int k = 0; k < maxc; k++) {
            bool act = k < cnt;
            float2 e = act ? sCand[w][lane][k] : make_float2(-INFINITY, 0.f);
            bool gt = act && (e.x >  thr);
            bool eq = act && (e.x == thr);
            unsigned mgt = __ballot_sync(0xffffffffu, gt);
            unsigned meq = __ballot_sync(0xffffffffu, eq);
            if (gt) {
                int p = cgt + __popc(mgt & lt);
                if (p < 8) sList[w][p] = e;
                sgt += e.x;
            }
            cgt += __popc(mgt);
            if (eq) {
                int p = ceq + __popc(meq & lt);
                if (p < 8) sList[w][8 + p] = e;
            }
            ceq += __popc(meq);
        }
        #pragma unroll
        for (int off = 16; off > 0; off >>= 1)
            sgt += __shfl_xor_sync(0xffffffffu, sgt, off);
        if (cgt + ceq == KK) {
            Mv = KK; cgtF = cgt;
            inv = 1.0f / (sgt + (float)ceq * thr);
            done = true;
        }
    }
    __syncwarp();

    float wreg = 0.f; int ireg = 0;
    if (done) {
        if (lane < KK) {
            float2 e = (lane < cgtF) ? sList[w][lane] : sList[w][8 + lane - cgtF];
            wreg = e.x; ireg = __float_as_int(e.y);
        }
    } else {
        int cgt = 0, ceq = 0;
        float sgt = 0.f;
        for (int t = 0; t < 16; t++) {
            int i4 = lane + t * 32;
            float4 f;
            if (i4 < 500) f = __ldg(&src4[i4]);
            else { f.x=f.y=f.z=f.w=-INFINITY; }
            bool any = (f.x >= thr) | (f.y >= thr) | (f.z >= thr) | (f.w >= thr);
            if (__ballot_sync(0xffffffffu, any) == 0u) continue;
            int ib = 4 * i4;
            #pragma unroll
            for (int s = 0; s < 4; s++) {
                float x = (s==0)?f.x:(s==1)?f.y:(s==2)?f.z:f.w;
                int   i = ib + s;
                bool gt = x >  thr;
                bool ge = x >= thr;
                unsigned mgt = __ballot_sync(0xffffffffu, gt);
                unsigned mge = __ballot_sync(0xffffffffu, ge);
                unsigned meq = mge & ~mgt;
                if (gt) {
                    int p = cgt + __popc(mgt & lt);
                    if (p < 8) sList[w][p] = make_float2(x, __int_as_float(i));
                    sgt += x;
                }
                cgt += __popc(mgt);
                if (meq) {
                    if (ge && !gt) {
                        int p = ceq + __popc(meq & lt);
                        if (p < 8) sList[w][8 + p] = make_float2(x, __int_as_float(i));
                    }
                    ceq += __popc(meq);
                }
            }
        }
        #pragma unroll
        for (int off = 16; off > 0; off >>= 1)
            sgt += __shfl_xor_sync(0xffffffffu, sgt, off);
        int eq_stored = ceq < 8 ? ceq : 8;
        Mv  = cgt + eq_stored;
        inv = 1.0f / (sgt + (float)ceq * thr);
        __syncwarp();
        if (lane < Mv) {
            float2 e = (lane < cgt) ? sList[w][lane] : sList[w][8 + lane - cgt];
            wreg = e.x; ireg = __float_as_int(e.y);
        }
    }
    __syncwarp();

    // --------- stage1 body (stats + Theta0 + tcn0) ---------
    float b0  = __ldg(&bias0[lane]), btc = __ldg(&bt0[lane]);
    ull t0m = pk2(__ldg(&Theta0[lane]),        __ldg(&Theta0[lane]));
    ull t0x = pk2(__ldg(&Theta0[CC+lane]),     __ldg(&Theta0[CC+lane]));
    ull t0n = pk2(__ldg(&Theta0[2*CC+lane]),   __ldg(&Theta0[2*CC+lane]));
    ull t0s = pk2(__ldg(&Theta0[3*CC+lane]),   __ldg(&Theta0[3*CC+lane]));
    float4 wv[8];
    #pragma unroll
    for (int q = 0; q < 8; q++) wv[q] = __ldg(&((const float4*)Wt0)[lane * 8 + q]);

    float sw0=0.f, sq0=0.f, mx0=-INFINITY, mn0=INFINITY;
    float sw1=0.f, sq1=0.f, mx1=-INFINITY, mn1=INFINITY;
    if (Mv == KK) {
        #pragma unroll
        for (int j = 0; j < KK; j++) {
            float wtj = __shfl_sync(0xffffffffu, wreg, j);
            int   mij = __shfl_sync(0xffffffffu, ireg, j);
            const float* xp = g_XT + mij * NBT;
            float x0 = __ldg(xp + lane);
            float x1 = (lane < 16) ? __ldg(xp + 32 + lane) : 0.f;
            float t0 = wtj * x0, t1 = wtj * x1;
            sw0 += t0; sq0 += t0 * x0;
            sw1 += t1; sq1 += t1 * x1;
            if (wtj > 0.f) {
                mx0 = fmaxf(mx0, x0); mn0 = fminf(mn0, x0);
                mx1 = fmaxf(mx1, x1); mn1 = fminf(mn1, x1);
            }
        }
    } else {
        for (int j = 0; j < Mv; j++) {
            float wtj = __shfl_sync(0xffffffffu, wreg, j);
            int   mij = __shfl_sync(0xffffffffu, ireg, j);
            const float* xp = g_XT + mij * NBT;
            float x0 = __ldg(xp + lane);
            float x1 = (lane < 16) ? __ldg(xp + 32 + lane) : 0.f;
            float t0 = wtj * x0, t1 = wtj * x1;
            sw0 += t0; sq0 += t0 * x0;
            sw1 += t1; sq1 += t1 * x1;
            if (j < KK && wtj > 0.f) {
                mx0 = fmaxf(mx0, x0); mn0 = fminf(mn0, x0);
                mx1 = fmaxf(mx1, x1); mn1 = fminf(mn1, x1);
            }
        }
    }
    {
        float mean = sw0 * inv;
        float sd = sqrtf(fmaxf(sq0 * inv - mean * mean, 0.f) + 1e-5f);
        sStat[w][lane] = make_float4(maskf(mean), maskf(mx0), maskf(mn0), maskf(sd));
    }
    if (lane < 16) {
        float mean = sw1 * inv;
        float sd = sqrtf(fmaxf(sq1 * inv - mean * mean, 0.f) + 1e-5f);
        sStat[w][32 + lane] = make_float4(maskf(mean), maskf(mx1), maskf(mn1), maskf(sd));
    }
    __syncwarp();

    ull b02 = pk2(b0, b0), btc2 = pk2(btc, btc);
    #pragma unroll
    for (int s = 0; s < NTB; s++) {
        int base = s * TB;
        float2* rp = &sR[w][0];
        ull racc[8];
        #pragma unroll
        for (int p = 0; p < 8; p++) {
            float4 A = sStat[w][base + 2 * p];
            float4 B = sStat[w][base + 2 * p + 1];
            ull o2 = b02;
            o2 = fma2(pk2(A.x, B.x), t0m, o2);
            o2 = fma2(pk2(A.y, B.y), t0x, o2);
            o2 = fma2(pk2(A.z, B.z), t0n, o2);
            o2 = fma2(pk2(A.w, B.w), t0s, o2);
            float f0, f1; upk2(o2, f0, f1);
            rp[p * CC + lane] = make_float2(f0, f1);
            racc[p] = o2;
        }
        __syncwarp();
        ull acc2[8];
        #pragma unroll
        for (int p = 0; p < 8; p++) acc2[p] = add2(btc2, racc[p]);
        #pragma unroll
        for (int q = 0; q < 8; q++) {
            ull wx = pk2(wv[q].x, wv[q].x), wy = pk2(wv[q].y, wv[q].y);
            ull wz = pk2(wv[q].z, wv[q].z), ww2 = pk2(wv[q].w, wv[q].w);
            #pragma unroll
            for (int p = 0; p < 8; p++) {
                const ulonglong2* rr = (const ulonglong2*)&rp[p * CC + 4 * q];
                ulonglong2 ra = rr[0];
                ulonglong2 rb = rr[1];
                acc2[p] = fma2(ra.x, wx, acc2[p]);
                acc2[p] = fma2(ra.y, wy, acc2[p]);
                acc2[p] = fma2(rb.x, wz, acc2[p]);
                acc2[p] = fma2(rb.y, ww2, acc2[p]);
            }
        }
        #pragma unroll
        for (int p = 0; p < 8; p++) {
            float a0, a1; upk2(acc2[p], a0, a1);
            int bt = base + 2 * p;
            g_h1[((size_t)bt * NN + n) * CC + lane]       = ftanh(a0);
            g_h1[((size_t)(bt + 1) * NN + n) * CC + lane] = ftanh(a1);
        }
        __syncwarp();
    }
}
#undef INS

// ================= K3: stage2, smem neighbor list, bounds (128,6) ===========
__global__ void __launch_bounds__(128, 6) stage2_kernel(const float* __restrict__ bias1,
                              const float* __restrict__ bt1,
                              const float* __restrict__ Wout,
                              const float* __restrict__ bout,
                              float* __restrict__ out) {
    __shared__ float4 sP[4][4][2][CC];   // 16 KB
    __shared__ float2 sLst[4][16];       // 512 B per-warp neighbor lists
    int tid = threadIdx.x;
    int lane = tid & 31;
    int w    = tid >> 5;

    float b1 = __ldg(&bias1[lane]), btc = __ldg(&bt1[lane]);
    float wo = __ldg(&Wout[lane]),  bo  = __ldg(&bout[0]);

    int grp = blockIdx.x * 4 + w;
    if (grp >= NG2) return;
    int n  = grp / NTB;
    int tb = grp - n * NTB;
    int bt0v = tb * TB;

    int M   = g_M[n];
    int cnt = g_cnt[n];
    float inv = g_inv[n];
    bool fast = (cnt == KK);

    if (lane < 16)
        sLst[w][lane] = (lane < M) ? g_nwi[n][lane] : make_float2(0.f, 0.f);
    __syncwarp();

    ull btc2 = pk2(btc, btc);

    #pragma unroll
    for (int ch = 0; ch < 2; ch++) {
        int btc0 = bt0v + ch * CH;
        float sw[CH], sq[CH], mxv[CH], mnv[CH];
        #pragma unroll
        for (int u = 0; u < CH; u++) {
            sw[u] = 0.f; sq[u] = 0.f; mxv[u] = -INFINITY; mnv[u] = INFINITY;
        }
        size_t cbase = (size_t)btc0 * NN * CC + lane;
        if (M == KK) {
            #pragma unroll
            for (int j = 0; j < KK; j++) {
                float2 wi = sLst[w][j];                  // uniform LDS
                const float* hp = g_h1 + cbase + (size_t)__float_as_int(wi.y) * CC;
                float wtj = wi.x;
                bool pos = wtj > 0.f;
                #pragma unroll
                for (int u = 0; u < CH; u++) {
                    float hv = __ldg(hp + (size_t)u * (NN * CC));
                    float t = wtj * hv;
                    sw[u] += t; sq[u] += t * hv;
                    if (pos) { mxv[u] = fmaxf(mxv[u], hv); mnv[u] = fminf(mnv[u], hv); }
                }
            }
        } else {
            for (int j = 0; j < M; j++) {
                float2 wi = sLst[w][j];
                const float* hp = g_h1 + cbase + (size_t)__float_as_int(wi.y) * CC;
                float wtj = wi.x;
                bool pos = (j < KK) && (wtj > 0.f);
                #pragma unroll
                for (int u = 0; u < CH; u++) {
                    float hv = __ldg(hp + (size_t)u * (NN * CC));
                    float t = wtj * hv;
                    sw[u] += t; sq[u] += t * hv;
                    if (pos) { mxv[u] = fmaxf(mxv[u], hv); mnv[u] = fminf(mnv[u], hv); }
                }
            }
        }
        #pragma unroll
        for (int u = 0; u < CH; u++) {
            float mean = sw[u] * inv;
            float sd = sqrtf(fmaxf(sq[u] * inv - mean * mean, 0.f) + 1e-5f);
            sw[u] = mean; sq[u] = sd;
        }
        #pragma unroll
        for (int p = 0; p < CH / 2; p++) {
            int u0 = 2 * p, u1 = 2 * p + 1;
            sP[w][p][0][lane] = make_float4(sw[u0], sw[u1], mxv[u0], mxv[u1]);
            sP[w][p][1][lane] = make_float4(mnv[u0], mnv[u1], sq[u0], sq[u1]);
        }
        __syncwarp();

        ull acc[4];
        #pragma unroll
        for (int p = 0; p < 4; p++) acc[p] = pk2(b1, b1);

        if (fast) {
            #pragma unroll 4
            for (int f = 0; f < CC; f++) {
                float4 wvv = __ldg(&g_Te3[f * CC + lane]);
                ull wx = pk2(wvv.x, wvv.x), wy = pk2(wvv.y, wvv.y);
                ull wz = pk2(wvv.z, wvv.z), ww2 = pk2(wvv.w, wvv.w);
                #pragma unroll
                for (int p = 0; p < 4; p++) {
                    ulonglong2 a = *(const ulonglong2*)&sP[w][p][0][f];
                    ulonglong2 bb = *(const ulonglong2*)&sP[w][p][1][f];
                    acc[p] = fma2(a.x, wx, acc[p]);
                    acc[p] = fma2(a.y, wy, acc[p]);
                    acc[p] = fma2(bb.x, wz, acc[p]);
                    acc[p] = fma2(bb.y, ww2, acc[p]);
                }
            }
        } else {
            float s  = log1pf((float)cnt);
            float is = 1.0f / s;
            for (int f = 0; f < CC; f++) {
                float4 a4 = __ldg(&g_TeA[f * CC + lane]);
                float4 b4 = __ldg(&g_TeB[f * CC + lane]);
                float4 c4 = __ldg(&g_TeC[f * CC + lane]);
                float4 wvv;
                wvv.x = a4.x + s * b4.x + is * c4.x;
                wvv.y = a4.y + s * b4.y + is * c4.y;
                wvv.z = a4.z + s * b4.z + is * c4.z;
                wvv.w = a4.w + s * b4.w + is * c4.w;
                ull wx = pk2(wvv.x, wvv.x), wy = pk2(wvv.y, wvv.y);
                ull wz = pk2(wvv.z, wvv.z), ww2 = pk2(wvv.w, wvv.w);
                #pragma unroll
                for (int p = 0; p < 4; p++) {
                    ulonglong2 a = *(const ulonglong2*)&sP[w][p][0][f];
                    ulonglong2 bb = *(const ulonglong2*)&sP[w][p][1][f];
                    acc[p] = fma2(a.x, wx, acc[p]);
                    acc[p] = fma2(a.y, wy, acc[p]);
                    acc[p] = fma2(bb.x, wz, acc[p]);
                    acc[p] = fma2(bb.y, ww2, acc[p]);
                }
            }
        }
        __syncwarp();

        float2* rp = (float2*)&sP[w][0][0][0];
        ull racc[4];
        #pragma unroll
        for (int p = 0; p < 4; p++) {
            float a0, a1; upk2(acc[p], a0, a1);
            float r0 = fmaxf(a0, 0.f), r1 = fmaxf(a1, 0.f);
            rp[p * 32 + lane] = make_float2(r0, r1);
            racc[p] = pk2(r0, r1);
        }
        __syncwarp();

        ull acc2[4];
        #pragma unroll
        for (int p = 0; p < 4; p++) acc2[p] = add2(btc2, racc[p]);
        #pragma unroll
        for (int q = 0; q < 8; q++) {
            float4 wq = __ldg(&g_Wt1v[q * CC + lane]);
            ull wx = pk2(wq.x, wq.x), wy = pk2(wq.y, wq.y);
            ull wz = pk2(wq.z, wq.z), ww2 = pk2(wq.w, wq.w);
            #pragma unroll
            for (int p = 0; p < 4; p++) {
                const ulonglong2* rr = (const ulonglong2*)&rp[p * 32 + 4 * q];
                ulonglong2 ra = rr[0];
                ulonglong2 rb = rr[1];
                acc2[p] = fma2(ra.x, wx, acc2[p]);
                acc2[p] = fma2(ra.y, wy, acc2[p]);
                acc2[p] = fma2(rb.x, wz, acc2[p]);
                acc2[p] = fma2(rb.y, ww2, acc2[p]);
            }
        }
        __syncwarp();

        #pragma unroll
        for (int p = 0; p < 4; p++) {
            float t0, t1; upk2(acc2[p], t0, t1);
            float u0 = fmaxf(ftanh(t0), 0.f);
            float u1 = fmaxf(ftanh(t1), 0.f);
            ull pu = pk2(wo * u0, wo * u1);
            #pragma unroll
            for (int off = 16; off > 0; off >>= 1)
                pu = add2(pu, __shfl_xor_sync(0xffffffffu, pu, off));
            if (lane == 0) {
                float s0, s1; upk2(pu, s0, s1);
                out[(size_t)(btc0 + 2 * p)     * NN + n] = s0 + bo;
                out[(size_t)(btc0 + 2 * p + 1) * NN + n] = s1 + bo;
            }
        }
        __syncwarp();
    }
}

extern "C" void kernel_launch(void* const* d_in, const int* in_sizes, int n_in,
                              void* d_out, int out_size) {
    const float* X      = (const float*)d_in[0];
    const float* adj    = (const float*)d_in[1];
    const float* adjm   = (const float*)d_in[2];
    const float* Theta0 = (const float*)d_in[3];
    const float* bias0  = (const float*)d_in[4];
    const float* Wt0    = (const float*)d_in[5];
    const float* bt0    = (const float*)d_in[6];
    const float* Theta1 = (const float*)d_in[7];
    const float* bias1  = (const float*)d_in[8];
    const float* Wt1    = (const float*)d_in[9];
    const float* bt1    = (const float*)d_in[10];
    const float* Wout   = (const float*)d_in[11];
    const float* bout   = (const float*)d_in[12];
    float* out = (float*)d_out;

    setup0_kernel<<<630, 256>>>(adj, Theta1, Wt1, X);
    stage1f_kernel<<<250, 256>>>(adjm, Theta0, bias0, Wt0, bt0);
    stage2_kernel<<<(NG2 + 3) / 4, 128>>>(bias1, bt1, Wout, bout, out);
}

// round 15
// speedup vs baseline: 1.1531x; 1.0062x over previous
#include <cuda_runtime.h>
#include <math.h>

#define Bb 4
#define Tt 12
#define NN 2000
#define KK 8
#define KMAX 16
#define CC 32
#define NBT (Bb*Tt)          // 48
#define TOT (Bb*Tt*NN)
#define TB  8                // bt per stage2 group (single chunk)
#define NTB (NBT/TB)         // 6
#define NG2 (NN*NTB)         // 12000 stage2 groups

// ---- scratch (no allocations allowed) ----
__device__ float2 g_nwi[NN][KMAX];     // adj top-k (weight, idx-as-bits)
__device__ int    g_M[NN];
__device__ int    g_cnt[NN];
__device__ float  g_inv[NN];
__device__ float  g_h1[(size_t)TOT * CC];
__device__ float  g_XT[NN * NBT];      // X transposed: [n][bt]
__device__ float4 g_Te3[CC * CC];      // folded Theta1 (s=log1p(8)): [f*32+o]={q0..q3}
__device__ float4 g_TeA[CC * CC];
__device__ float4 g_TeB[CC * CC];
__device__ float4 g_TeC[CC * CC];
__device__ float4 g_Wt1v[8 * CC];      // Wt1: [q*32+o] = Wt1[o][4q..4q+3]

typedef unsigned long long ull;

__device__ __forceinline__ float maskf(float v) {
    if (isnan(v)) v = 6.0f;
    if (isinf(v)) v = 0.0f;
    return fminf(v, 6.0f);
}
__device__ __forceinline__ float ftanh(float x) {
    float e = __expf(2.0f * x);
    return 1.0f - __fdividef(2.0f, e + 1.0f);
}
__device__ __forceinline__ ull pk2(float a, float b) {
    ull r; asm("mov.b64 %0, {%1,%2};" : "=l"(r) : "f"(a), "f"(b)); return r;
}
__device__ __forceinline__ void upk2(ull v, float& a, float& b) {
    asm("mov.b64 {%0,%1}, %2;" : "=f"(a), "=f"(b) : "l"(v));
}
__device__ __forceinline__ ull fma2(ull a, ull b, ull c) {
    ull d; asm("fma.rn.f32x2 %0, %1, %2, %3;" : "=l"(d) : "l"(a), "l"(b), "l"(c)); return d;
}
__device__ __forceinline__ ull add2(ull a, ull b) {
    ull d; asm("add.rn.f32x2 %0, %1, %2;" : "=l"(d) : "l"(a), "l"(b)); return d;
}
// order-preserving float<->uint (total order incl. -inf)
__device__ __forceinline__ unsigned ford(float x) {
    unsigned u = __float_as_uint(x);
    return ((int)u >= 0) ? (u | 0x80000000u) : ~u;
}
__device__ __forceinline__ float funord(unsigned o) {
    unsigned u = (o & 0x80000000u) ? (o & 0x7fffffffu) : ~o;
    return __uint_as_float(u);
}

#define INS(xx) do { float x_ = (xx); \
    v7 = fmaxf(v7, fminf(v6, x_)); \
    v6 = fmaxf(v6, fminf(v5, x_)); \
    v5 = fmaxf(v5, fminf(v4, x_)); \
    v4 = fmaxf(v4, fminf(v3, x_)); \
    v3 = fmaxf(v3, fminf(v2, x_)); \
    v2 = fmaxf(v2, fminf(v1, x_)); \
    v1 = fmaxf(v1, fminf(v0, x_)); \
    v0 = fmaxf(v0, x_); } while(0)

#define MERGE8_THR() do { \
    _Pragma("unroll") \
    for (int k_ = 0; k_ < 8; k_++) { \
        unsigned mo_ = __reduce_max_sync(0xffffffffu, ford(v0)); \
        thr = funord(mo_); \
        unsigned msk_ = __ballot_sync(0xffffffffu, ford(v0) == mo_); \
        if (lane == (__ffs(msk_) - 1)) { \
            v0=v1; v1=v2; v2=v3; v3=v4; v4=v5; v5=v6; v6=v7; v7=-INFINITY; \
        } \
    } \
} while(0)

// ================= K1: topk(adj) [blocks 0-249] + prep [250-254] + XT [255-629]
__global__ void __launch_bounds__(256) setup0_kernel(const float* __restrict__ adj,
                                                     const float* __restrict__ Theta1,
                                                     const float* __restrict__ Wt1,
                                                     const float* __restrict__ X) {
    __shared__ float2 sCand[8][32][8];    // 16 KB
    int b = blockIdx.x;
    int tid = threadIdx.x;
    if (b >= 255) {
        int idx = (b - 255) * 256 + tid;
        g_XT[idx] = X[(idx % NBT) * NN + idx / NBT];
        return;
    }
    if (b >= 250) {
        int idx = (b - 250) * 256 + tid;
        if (idx < CC * CC) {
            int f = idx >> 5, o = idx & 31;
            const float s8  = log1pf(8.0f);
            const float is8 = 1.0f / s8;
            float4 va, vb, vc, ve;
            float *pa=(float*)&va, *pb=(float*)&vb, *pc=(float*)&vc, *pe=(float*)&ve;
            #pragma unroll
            for (int q = 0; q < 4; q++) {
                int src = (q * CC + f) * CC + o;
                float A = Theta1[src];
                float B = Theta1[4*CC*CC + src];
                float C = Theta1[8*CC*CC + src];
                pa[q] = A; pb[q] = B; pc[q] = C;
                pe[q] = A + s8 * B + is8 * C;
            }
            g_TeA[idx] = va; g_TeB[idx] = vb; g_TeC[idx] = vc; g_Te3[idx] = ve;
        } else if (idx < CC * CC + 8 * CC) {
            int i = idx - CC * CC;
            int q = i >> 5, o = i & 31;
            g_Wt1v[i] = ((const float4*)Wt1)[o * 8 + q];
        }
        return;
    }
    // ---- top-K of adj: warp per row ----
    int w = tid >> 5;
    int row = b * 8 + w;
    const float4* src4 = (const float4*)(adj + (size_t)row * NN);
    int lane = tid & 31;
    unsigned lt = (1u << lane) - 1u;

    const float CUT = 0.99f;
    int cnt = 0;
    #pragma unroll
    for (int t = 0; t < 16; t++) {
        int i4 = lane + t * 32;
        float4 f;
        if (i4 < 500) f = __ldg(&src4[i4]);
        else { f.x=f.y=f.z=f.w=-INFINITY; }
        int ib = 4 * i4;
        #pragma unroll
        for (int s = 0; s < 4; s++) {
            float x = (s==0)?f.x:(s==1)?f.y:(s==2)?f.z:f.w;
            if (x > CUT) {
                if (cnt < 8) sCand[w][lane][cnt] = make_float2(x, __int_as_float(ib + s));
                cnt++;
            }
        }
    }
    int total = __reduce_add_sync(0xffffffffu, (unsigned)cnt);
    int maxc  = __reduce_max_sync(0xffffffffu, (unsigned)cnt);
    bool fastp = (total >= KK) && (maxc <= 8);

    float v0=-INFINITY,v1=-INFINITY,v2=-INFINITY,v3=-INFINITY,
          v4=-INFINITY,v5=-INFINITY,v6=-INFINITY,v7=-INFINITY;
    if (fastp) {
        for (int k = 0; k < cnt; k++) INS(sCand[w][lane][k].x);
    } else {
        for (int t = 0; t < 16; t++) {
            int i4 = lane + t * 32;
            if (i4 < 500) {
                float4 f = __ldg(&src4[i4]);
                INS(f.x); INS(f.y); INS(f.z); INS(f.w);
            }
        }
    }

    float thr = -INFINITY;
    MERGE8_THR();

    bool done = false;
    if (fastp) {
        int cgt = 0, ceq = 0;
        float sgt = 0.f;
        for (int k = 0; k < maxc; k++) {
            bool act = k < cnt;
            float2 e = act ? sCand[w][lane][k] : make_float2(-INFINITY, 0.f);
            bool gt = act && (e.x >  thr);
            bool eq = act && (e.x == thr);
            unsigned mgt = __ballot_sync(0xffffffffu, gt);
            unsigned meq = __ballot_sync(0xffffffffu, eq);
            if (gt) {
                int p = cgt + __popc(mgt & lt);
                if (p < 8) g_nwi[row][p] = e;
                sgt += e.x;
            }
            cgt += __popc(mgt);
            if (eq) {
                int p = ceq + __popc(meq & lt);
                if (p < 8) g_nwi[row][8 + p] = e;
            }
            ceq += __popc(meq);
        }
        #pragma unroll
        for (int off = 16; off > 0; off >>= 1)
            sgt += __shfl_xor_sync(0xffffffffu, sgt, off);
        if (cgt + ceq == KK) {
            if (lane == 0) {
                for (int e2 = 0; e2 < ceq; e2++)
                    g_nwi[row][cgt + e2] = g_nwi[row][8 + e2];
                g_M[row]   = KK;
                g_cnt[row] = KK;
                g_inv[row] = 1.0f / (sgt + (float)ceq * thr);
            }
            done = true;
        }
    }

    if (!done) {
        int cgt = 0, ceq = 0;
        float sgt = 0.f;
        for (int t = 0; t < 16; t++) {
            int i4 = lane + t * 32;
            float4 f;
            if (i4 < 500) f = __ldg(&src4[i4]);
            else { f.x=f.y=f.z=f.w=-INFINITY; }
            bool any = (f.x >= thr) | (f.y >= thr) | (f.z >= thr) | (f.w >= thr);
            if (__ballot_sync(0xffffffffu, any) == 0u) continue;
            int ib = 4 * i4;
            #pragma unroll
            for (int s = 0; s < 4; s++) {
                float x = (s==0)?f.x:(s==1)?f.y:(s==2)?f.z:f.w;
                int   i = ib + s;
                bool gt = x >  thr;
                bool ge = x >= thr;
                unsigned mgt = __ballot_sync(0xffffffffu, gt);
                unsigned mge = __ballot_sync(0xffffffffu, ge);
                unsigned meq = mge & ~mgt;
                if (gt) {
                    int p = cgt + __popc(mgt & lt);
                    g_nwi[row][p] = make_float2(x, __int_as_float(i));
                    sgt += x;
                }
                cgt += __popc(mgt);
                if (meq) {
                    if (ge && !gt) {
                        int p = ceq + __popc(meq & lt);
                        if (p < 8) g_nwi[row][8 + p] = make_float2(x, __int_as_float(i));
                    }
                    ceq += __popc(meq);
                }
            }
        }
        #pragma unroll
        for (int off = 16; off > 0; off >>= 1)
            sgt += __shfl_xor_sync(0xffffffffu, sgt, off);

        if (lane == 0) {
            int cnt2 = cgt + ceq;
            int eq_stored = ceq < 8 ? ceq : 8;
            int M = cgt + eq_stored;
            for (int e2 = 0; e2 < eq_stored; e2++)
                g_nwi[row][cgt + e2] = g_nwi[row][8 + e2];
            g_M[row]   = M;
            g_cnt[row] = cnt2;
            g_inv[row] = 1.0f / (sgt + (float)ceq * thr);
        }
    }
}

// ================= K2: fused topk(adjm) + stage1, warp per n =====
__global__ void __launch_bounds__(256) stage1f_kernel(const float* __restrict__ adjm,
                              const float* __restrict__ Theta0,
                              const float* __restrict__ bias0,
                              const float* __restrict__ Wt0,
                              const float* __restrict__ bt0) {
    __shared__ float2 sCand[8][32][8];   // 16 KB
    __shared__ float2 sList[8][16];      // 1 KB  (slots [0..8)=gt, [8..16)=eq)
    __shared__ float4 sStat[8][NBT];     // 6 KB
    __shared__ float2 sR[8][8 * CC];     // 16 KB
    int tid = threadIdx.x;
    int lane = tid & 31;
    int w    = tid >> 5;
    int n = blockIdx.x * 8 + w;
    unsigned lt = (1u << lane) - 1u;

    const float4* src4 = (const float4*)(adjm + (size_t)n * NN);
    const float CUT = 0.99f;
    int cnt = 0;
    #pragma unroll
    for (int t = 0; t < 16; t++) {
        int i4 = lane + t * 32;
        float4 f;
        if (i4 < 500) f = __ldg(&src4[i4]);
        else { f.x=f.y=f.z=f.w=-INFINITY; }
        int ib = 4 * i4;
        #pragma unroll
        for (int s = 0; s < 4; s++) {
            float x = (s==0)?f.x:(s==1)?f.y:(s==2)?f.z:f.w;
            if (x > CUT) {
                if (cnt < 8) sCand[w][lane][cnt] = make_float2(x, __int_as_float(ib + s));
                cnt++;
            }
        }
    }
    int total = __reduce_add_sync(0xffffffffu, (unsigned)cnt);
    int maxc  = __reduce_max_sync(0xffffffffu, (unsigned)cnt);
    bool fastp = (total >= KK) && (maxc <= 8);

    float v0=-INFINITY,v1=-INFINITY,v2=-INFINITY,v3=-INFINITY,
          v4=-INFINITY,v5=-INFINITY,v6=-INFINITY,v7=-INFINITY;
    if (fastp) {
        for (int k = 0; k < cnt; k++) INS(sCand[w][lane][k].x);
    } else {
        for (int t = 0; t < 16; t++) {
            int i4 = lane + t * 32;
            if (i4 < 500) {
                float4 f = __ldg(&src4[i4]);
                INS(f.x); INS(f.y); INS(f.z); INS(f.w);
            }
        }
    }

    float thr = -INFINITY;
    MERGE8_THR();

    int Mv = 0;
    int cgtF = 0;
    float inv = 0.f;
    bool done = false;
    if (fastp) {
        int cgt = 0, ceq = 0;
        float sgt = 0.f;
        for (int k = 0; k < maxc; k++) {
            bool act = k < cnt;
            float2 e = act ? sCand[w][lane][k] : make_float2(-INFINITY, 0.f);
            bool gt = act && (e.x >  thr);
            bool eq = act && (e.x == thr);
            unsigned mgt = __ballot_sync(0xffffffffu, gt);
            unsigned meq = __ballot_sync(0xffffffffu, eq);
            if (gt) {
                int p = cgt + __popc(mgt & lt);
                if (p < 8) sList[w][p] = e;
                sgt += e.x;
            }
            cgt += __popc(mgt);
            if (eq) {
                int p = ceq + __popc(meq & lt);
                if (p < 8) sList[w][8 + p] = e;
            }
            ceq += __popc(meq);
        }
        #pragma unroll
        for (int off = 16; off > 0; off >>= 1)
            sgt += __shfl_xor_sync(0xffffffffu, sgt, off);
        if (cgt + ceq == KK) {
            Mv = KK; cgtF = cgt;
            inv = 1.0f / (sgt + (float)ceq * thr);
            done = true;
        }
    }
    __syncwarp();

    float wreg = 0.f; int ireg = 0;
    if (done) {
        if (lane < KK) {
            float2 e = (lane < cgtF) ? sList[w][lane] : sList[w][8 + lane - cgtF];
            wreg = e.x; ireg = __float_as_int(e.y);
        }
    } else {
        int cgt = 0, ceq = 0;
        float sgt = 0.f;
        for (int t = 0; t < 16; t++) {
            int i4 = lane + t * 32;
            float4 f;
            if (i4 < 500) f = __ldg(&src4[i4]);
            else { f.x=f.y=f.z=f.w=-INFINITY; }
            bool any = (f.x >= thr) | (f.y >= thr) | (f.z >= thr) | (f.w >= thr);
            if (__ballot_sync(0xffffffffu, any) == 0u) continue;
            int ib = 4 * i4;
            #pragma unroll
            for (int s = 0; s < 4; s++) {
                float x = (s==0)?f.x:(s==1)?f.y:(s==2)?f.z:f.w;
                int   i = ib + s;
                bool gt = x >  thr;
                bool ge = x >= thr;
                unsigned mgt = __ballot_sync(0xffffffffu, gt);
                unsigned mge = __ballot_sync(0xffffffffu, ge);
                unsigned meq = mge & ~mgt;
                if (gt) {
                    int p = cgt + __popc(mgt & lt);
                    if (p < 8) sList[w][p] = make_float2(x, __int_as_float(i));
                    sgt += x;
                }
                cgt += __popc(mgt);
                if (meq) {
                    if (ge && !gt) {
                        int p = ceq + __popc(meq & lt);
                        if (p < 8) sList[w][8 + p] = make_float2(x, __int_as_float(i));
                    }
                    ceq += __popc(meq);
                }
            }
        }
        #pragma unroll
        for (int off = 16; off > 0; off >>= 1)
            sgt += __shfl_xor_sync(0xffffffffu, sgt, off);
        int eq_stored = ceq < 8 ? ceq : 8;
        Mv  = cgt + eq_stored;
        inv = 1.0f / (sgt + (float)ceq * thr);
        __syncwarp();
        if (lane < Mv) {
            float2 e = (lane < cgt) ? sList[w][lane] : sList[w][8 + lane - cgt];
            wreg = e.x; ireg = __float_as_int(e.y);
        }
    }
    __syncwarp();

    // --------- stage1 body (stats + Theta0 + tcn0) ---------
    float b0  = __ldg(&bias0[lane]), btc = __ldg(&bt0[lane]);
    ull t0m = pk2(__ldg(&Theta0[lane]),        __ldg(&Theta0[lane]));
    ull t0x = pk2(__ldg(&Theta0[CC+lane]),     __ldg(&Theta0[CC+lane]));
    ull t0n = pk2(__ldg(&Theta0[2*CC+lane]),   __ldg(&Theta0[2*CC+lane]));
    ull t0s = pk2(__ldg(&Theta0[3*CC+lane]),   __ldg(&Theta0[3*CC+lane]));
    float4 wv[8];
    #pragma unroll
    for (int q = 0; q < 8; q++) wv[q] = __ldg(&((const float4*)Wt0)[lane * 8 + q]);

    float sw0=0.f, sq0=0.f, mx0=-INFINITY, mn0=INFINITY;
    float sw1=0.f, sq1=0.f, mx1=-INFINITY, mn1=INFINITY;
    if (Mv == KK) {
        #pragma unroll
        for (int j = 0; j < KK; j++) {
            float wtj = __shfl_sync(0xffffffffu, wreg, j);
            int   mij = __shfl_sync(0xffffffffu, ireg, j);
            const float* xp = g_XT + mij * NBT;
            float x0 = __ldg(xp + lane);
            float x1 = (lane < 16) ? __ldg(xp + 32 + lane) : 0.f;
            float t0 = wtj * x0, t1 = wtj * x1;
            sw0 += t0; sq0 += t0 * x0;
            sw1 += t1; sq1 += t1 * x1;
            if (wtj > 0.f) {
                mx0 = fmaxf(mx0, x0); mn0 = fminf(mn0, x0);
                mx1 = fmaxf(mx1, x1); mn1 = fminf(mn1, x1);
            }
        }
    } else {
        for (int j = 0; j < Mv; j++) {
            float wtj = __shfl_sync(0xffffffffu, wreg, j);
            int   mij = __shfl_sync(0xffffffffu, ireg, j);
            const float* xp = g_XT + mij * NBT;
            float x0 = __ldg(xp + lane);
            float x1 = (lane < 16) ? __ldg(xp + 32 + lane) : 0.f;
            float t0 = wtj * x0, t1 = wtj * x1;
            sw0 += t0; sq0 += t0 * x0;
            sw1 += t1; sq1 += t1 * x1;
            if (j < KK && wtj > 0.f) {
                mx0 = fmaxf(mx0, x0); mn0 = fminf(mn0, x0);
                mx1 = fmaxf(mx1, x1); mn1 = fminf(mn1, x1);
            }
        }
    }
    {
        float mean = sw0 * inv;
        float sd = sqrtf(fmaxf(sq0 * inv - mean * mean, 0.f) + 1e-5f);
        sStat[w][lane] = make_float4(maskf(mean), maskf(mx0), maskf(mn0), maskf(sd));
    }
    if (lane < 16) {
        float mean = sw1 * inv;
        float sd = sqrtf(fmaxf(sq1 * inv - mean * mean, 0.f) + 1e-5f);
        sStat[w][32 + lane] = make_float4(maskf(mean), maskf(mx1), maskf(mn1), maskf(sd));
    }
    __syncwarp();

    ull b02 = pk2(b0, b0), btc2 = pk2(btc, btc);
    #pragma unroll
    for (int s = 0; s < 3; s++) {
        int base = s * 16;
        float2* rp = &sR[w][0];
        ull racc[8];
        #pragma unroll
        for (int p = 0; p < 8; p++) {
            float4 A = sStat[w][base + 2 * p];
            float4 B = sStat[w][base + 2 * p + 1];
            ull o2 = b02;
            o2 = fma2(pk2(A.x, B.x), t0m, o2);
            o2 = fma2(pk2(A.y, B.y), t0x, o2);
            o2 = fma2(pk2(A.z, B.z), t0n, o2);
            o2 = fma2(pk2(A.w, B.w), t0s, o2);
            float f0, f1; upk2(o2, f0, f1);
            rp[p * CC + lane] = make_float2(f0, f1);
            racc[p] = o2;
        }
        __syncwarp();
        ull acc2[8];
        #pragma unroll
        for (int p = 0; p < 8; p++) acc2[p] = add2(btc2, racc[p]);
        #pragma unroll
        for (int q = 0; q < 8; q++) {
            ull wx = pk2(wv[q].x, wv[q].x), wy = pk2(wv[q].y, wv[q].y);
            ull wz = pk2(wv[q].z, wv[q].z), ww2 = pk2(wv[q].w, wv[q].w);
            #pragma unroll
            for (int p = 0; p < 8; p++) {
                const ulonglong2* rr = (const ulonglong2*)&rp[p * CC + 4 * q];
                ulonglong2 ra = rr[0];
                ulonglong2 rb = rr[1];
                acc2[p] = fma2(ra.x, wx, acc2[p]);
                acc2[p] = fma2(ra.y, wy, acc2[p]);
                acc2[p] = fma2(rb.x, wz, acc2[p]);
                acc2[p] = fma2(rb.y, ww2, acc2[p]);
            }
        }
        #pragma unroll
        for (int p = 0; p < 8; p++) {
            float a0, a1; upk2(acc2[p], a0, a1);
            int bt = base + 2 * p;
            g_h1[((size_t)bt * NN + n) * CC + lane]       = ftanh(a0);
            g_h1[((size_t)(bt + 1) * NN + n) * CC + lane] = ftanh(a1);
        }
        __syncwarp();
    }
}
#undef INS

// ================= K3: stage2, TB=8 single-chunk ============================
__global__ void __launch_bounds__(128) stage2_kernel(const float* __restrict__ bias1,
                              const float* __restrict__ bt1,
                              const float* __restrict__ Wout,
                              const float* __restrict__ bout,
                              float* __restrict__ out) {
    __shared__ float4 sP[4][4][2][CC];   // 16 KB: [warp][pair][half][f]
    __shared__ float2 sLst[4][16];       // 512 B per-warp neighbor lists
    int tid = threadIdx.x;
    int lane = tid & 31;
    int w    = tid >> 5;

    float b1 = __ldg(&bias1[lane]), btc = __ldg(&bt1[lane]);
    float wo = __ldg(&Wout[lane]),  bo  = __ldg(&bout[0]);

    int grp = blockIdx.x * 4 + w;
    if (grp >= NG2) return;
    int n  = grp / NTB;
    int tb = grp - n * NTB;
    int bt0v = tb * TB;

    int M   = g_M[n];
    int cnt = g_cnt[n];
    float inv = g_inv[n];
    bool fast = (cnt == KK);

    if (lane < 16)
        sLst[w][lane] = (lane < M) ? g_nwi[n][lane] : make_float2(0.f, 0.f);
    __syncwarp();

    ull btc2 = pk2(btc, btc);

    // ---- phase A: stats for 8 bt ----
    float sw[TB], sq[TB], mxv[TB], mnv[TB];
    #pragma unroll
    for (int u = 0; u < TB; u++) {
        sw[u] = 0.f; sq[u] = 0.f; mxv[u] = -INFINITY; mnv[u] = INFINITY;
    }
    size_t cbase = (size_t)bt0v * NN * CC + lane;
    if (M == KK) {
        #pragma unroll
        for (int j = 0; j < KK; j++) {
            float2 wi = sLst[w][j];                  // uniform LDS
            const float* hp = g_h1 + cbase + (size_t)__float_as_int(wi.y) * CC;
            float wtj = wi.x;
            bool pos = wtj > 0.f;
            #pragma unroll
            for (int u = 0; u < TB; u++) {
                float hv = __ldg(hp + (size_t)u * (NN * CC));
                float t = wtj * hv;
                sw[u] += t; sq[u] += t * hv;
                if (pos) { mxv[u] = fmaxf(mxv[u], hv); mnv[u] = fminf(mnv[u], hv); }
            }
        }
    } else {
        for (int j = 0; j < M; j++) {
            float2 wi = sLst[w][j];
            const float* hp = g_h1 + cbase + (size_t)__float_as_int(wi.y) * CC;
            float wtj = wi.x;
            bool pos = (j < KK) && (wtj > 0.f);
            #pragma unroll
            for (int u = 0; u < TB; u++) {
                float hv = __ldg(hp + (size_t)u * (NN * CC));
                float t = wtj * hv;
                sw[u] += t; sq[u] += t * hv;
                if (pos) { mxv[u] = fmaxf(mxv[u], hv); mnv[u] = fminf(mnv[u], hv); }
            }
        }
    }
    #pragma unroll
    for (int u = 0; u < TB; u++) {
        float mean = sw[u] * inv;
        float sd = sqrtf(fmaxf(sq[u] * inv - mean * mean, 0.f) + 1e-5f);
        sw[u] = mean; sq[u] = sd;
    }
    #pragma unroll
    for (int p = 0; p < TB / 2; p++) {
        int u0 = 2 * p, u1 = 2 * p + 1;
        sP[w][p][0][lane] = make_float4(sw[u0], sw[u1], mxv[u0], mxv[u1]);
        sP[w][p][1][lane] = make_float4(mnv[u0], mnv[u1], sq[u0], sq[u1]);
    }
    __syncwarp();

    // ---- phase B: Theta matmul (f32x2), 4 pairs ----
    ull acc[4];
    #pragma unroll
    for (int p = 0; p < 4; p++) acc[p] = pk2(b1, b1);

    if (fast) {
        #pragma unroll 4
        for (int f = 0; f < CC; f++) {
            float4 wvv = __ldg(&g_Te3[f * CC + lane]);
            ull wx = pk2(wvv.x, wvv.x), wy = pk2(wvv.y, wvv.y);
            ull wz = pk2(wvv.z, wvv.z), ww2 = pk2(wvv.w, wvv.w);
            #pragma unroll
            for (int p = 0; p < 4; p++) {
                ulonglong2 a = *(const ulonglong2*)&sP[w][p][0][f];
                ulonglong2 bb = *(const ulonglong2*)&sP[w][p][1][f];
                acc[p] = fma2(a.x, wx, acc[p]);
                acc[p] = fma2(a.y, wy, acc[p]);
                acc[p] = fma2(bb.x, wz, acc[p]);
                acc[p] = fma2(bb.y, ww2, acc[p]);
            }
        }
    } else {
        float s  = log1pf((float)cnt);
        float is = 1.0f / s;
        for (int f = 0; f < CC; f++) {
            float4 a4 = __ldg(&g_TeA[f * CC + lane]);
            float4 b4 = __ldg(&g_TeB[f * CC + lane]);
            float4 c4 = __ldg(&g_TeC[f * CC + lane]);
            float4 wvv;
            wvv.x = a4.x + s * b4.x + is * c4.x;
            wvv.y = a4.y + s * b4.y + is * c4.y;
            wvv.z = a4.z + s * b4.z + is * c4.z;
            wvv.w = a4.w + s * b4.w + is * c4.w;
            ull wx = pk2(wvv.x, wvv.x), wy = pk2(wvv.y, wvv.y);
            ull wz = pk2(wvv.z, wvv.z), ww2 = pk2(wvv.w, wvv.w);
            #pragma unroll
            for (int p = 0; p < 4; p++) {
                ulonglong2 a = *(const ulonglong2*)&sP[w][p][0][f];
                ulonglong2 bb = *(const ulonglong2*)&sP[w][p][1][f];
                acc[p] = fma2(a.x, wx, acc[p]);
                acc[p] = fma2(a.y, wy, acc[p]);
                acc[p] = fma2(bb.x, wz, acc[p]);
                acc[p] = fma2(bb.y, ww2, acc[p]);
            }
        }
    }
    __syncwarp();

    // ---- phase C: relu -> tcn1 (f32x2) ----
    float2* rp = (float2*)&sP[w][0][0][0];
    ull racc[4];
    #pragma unroll
    for (int p = 0; p < 4; p++) {
        float a0, a1; upk2(acc[p], a0, a1);
        float r0 = fmaxf(a0, 0.f), r1 = fmaxf(a1, 0.f);
        rp[p * 32 + lane] = make_float2(r0, r1);
        racc[p] = pk2(r0, r1);
    }
    __syncwarp();

    ull acc2[4];
    #pragma unroll
    for (int p = 0; p < 4; p++) acc2[p] = add2(btc2, racc[p]);
    #pragma unroll
    for (int q = 0; q < 8; q++) {
        float4 wq = __ldg(&g_Wt1v[q * CC + lane]);
        ull wx = pk2(wq.x, wq.x), wy = pk2(wq.y, wq.y);
        ull wz = pk2(wq.z, wq.z), ww2 = pk2(wq.w, wq.w);
        #pragma unroll
        for (int p = 0; p < 4; p++) {
            const ulonglong2* rr = (const ulonglong2*)&rp[p * 32 + 4 * q];
            ulonglong2 ra = rr[0];
            ulonglong2 rb = rr[1];
            acc2[p] = fma2(ra.x, wx, acc2[p]);
            acc2[p] = fma2(ra.y, wy, acc2[p]);
            acc2[p] = fma2(rb.x, wz, acc2[p]);
            acc2[p] = fma2(rb.y, ww2, acc2[p]);
        }
    }
    __syncwarp();

    // ---- head ----
    #pragma unroll
    for (int p = 0; p < 4; p++) {
        float t0, t1; upk2(acc2[p], t0, t1);
        float u0 = fmaxf(ftanh(t0), 0.f);
        float u1 = fmaxf(ftanh(t1), 0.f);
        ull pu = pk2(wo * u0, wo * u1);
        #pragma unroll
        for (int off = 16; off > 0; off >>= 1)
            pu = add2(pu, __shfl_xor_sync(0xffffffffu, pu, off));
        if (lane == 0) {
            float s0, s1; upk2(pu, s0, s1);
            out[(size_t)(bt0v + 2 * p)     * NN + n] = s0 + bo;
            out[(size_t)(bt0v + 2 * p + 1) * NN + n] = s1 + bo;
        }
    }
}

extern "C" void kernel_launch(void* const* d_in, const int* in_sizes, int n_in,
                              void* d_out, int out_size) {
    const float* X      = (const float*)d_in[0];
    const float* adj    = (const float*)d_in[1];
    const float* adjm   = (const float*)d_in[2];
    const float* Theta0 = (const float*)d_in[3];
    const float* bias0  = (const float*)d_in[4];
    const float* Wt0    = (const float*)d_in[5];
    const float* bt0    = (const float*)d_in[6];
    const float* Theta1 = (const float*)d_in[7];
    const float* bias1  = (const float*)d_in[8];
    const float* Wt1    = (const float*)d_in[9];
    const float* bt1    = (const float*)d_in[10];
    const float* Wout   = (const float*)d_in[11];
    const float* bout   = (const float*)d_in[12];
    float* out = (float*)d_out;

    setup0_kernel<<<630, 256>>>(adj, Theta1, Wt1, X);
    stage1f_kernel<<<250, 256>>>(adjm, Theta0, bias0, Wt0, bt0);
    stage2_kernel<<<NG2 / 4, 128>>>(bias1, bt1, Wout, bout, out);
}